// round 3
// baseline (speedup 1.0000x reference)
#include <cuda_runtime.h>

// Fused Poincare-ball: y = proj(expmap0(relu(logmap0(x))))
// 4 threads per row (D=64). Each thread handles TWO consecutive rows:
// 8 front-batched LDG.128 per thread (MLP=8) to saturate HBM at low occupancy.

#define MIN_NORM  1e-7f
#define BALL_EPS  4e-3f
#define ATANH_EPS 1e-7f

__global__ __launch_bounds__(256)
void act_hyp_kernel(const float4* __restrict__ x,
                    const float* __restrict__ c,
                    float4* __restrict__ out,
                    int nrows)
{
    const int t    = blockIdx.x * blockDim.x + threadIdx.x;
    const int lane = t & 3;
    const int rowA = (t >> 2) * 2;       // this group's first row
    if (rowA >= nrows) return;
    const int rowB = rowA + 1;

    const float4* xpA = x + (size_t)rowA * 16 + lane;

    // Front-batch 8 x LDG.128: rows A and B (row stride = 16 float4)
    float4 v[8];
    #pragma unroll
    for (int i = 0; i < 4; i++) v[i]     = __ldcs(xpA + i * 4);
    #pragma unroll
    for (int i = 0; i < 4; i++) v[4 + i] = __ldcs(xpA + 16 + i * 4);

    // Per-row squared sums of x and relu(x)
    float s2A = 0.f, s2pA = 0.f, s2B = 0.f, s2pB = 0.f;
    #pragma unroll
    for (int i = 0; i < 4; i++) {
        float a0 = v[i].x, a1 = v[i].y, a2 = v[i].z, a3 = v[i].w;
        s2A = fmaf(a0, a0, s2A); s2A = fmaf(a1, a1, s2A);
        s2A = fmaf(a2, a2, s2A); s2A = fmaf(a3, a3, s2A);
        float b0 = fmaxf(a0, 0.f), b1 = fmaxf(a1, 0.f);
        float b2 = fmaxf(a2, 0.f), b3 = fmaxf(a3, 0.f);
        s2pA = fmaf(b0, b0, s2pA); s2pA = fmaf(b1, b1, s2pA);
        s2pA = fmaf(b2, b2, s2pA); s2pA = fmaf(b3, b3, s2pA);
    }
    #pragma unroll
    for (int i = 4; i < 8; i++) {
        float a0 = v[i].x, a1 = v[i].y, a2 = v[i].z, a3 = v[i].w;
        s2B = fmaf(a0, a0, s2B); s2B = fmaf(a1, a1, s2B);
        s2B = fmaf(a2, a2, s2B); s2B = fmaf(a3, a3, s2B);
        float b0 = fmaxf(a0, 0.f), b1 = fmaxf(a1, 0.f);
        float b2 = fmaxf(a2, 0.f), b3 = fmaxf(a3, 0.f);
        s2pB = fmaf(b0, b0, s2pB); s2pB = fmaf(b1, b1, s2pB);
        s2pB = fmaf(b2, b2, s2pB); s2pB = fmaf(b3, b3, s2pB);
    }

    // 4-lane xor reduction (groups of 4 aligned within the warp)
    #pragma unroll
    for (int off = 2; off >= 1; off >>= 1) {
        s2A  += __shfl_xor_sync(0xFFFFFFFFu, s2A,  off);
        s2pA += __shfl_xor_sync(0xFFFFFFFFu, s2pA, off);
        s2B  += __shfl_xor_sync(0xFFFFFFFFu, s2B,  off);
        s2pB += __shfl_xor_sync(0xFFFFFFFFu, s2pB, off);
    }

    const float sqrt_c  = sqrtf(c[0]);
    const float maxnorm = __fdividef(1.0f - BALL_EPS, sqrt_c);

    // Per-row scalar: m = f * t * projscale
    auto row_scale = [&](float s2, float s2p) -> float {
        float xn  = fmaxf(sqrtf(s2), MIN_NORM);
        float sxn = sqrt_c * xn;
        float arg = fminf(sxn, 1.0f - ATANH_EPS);
        // atanh(a) = 0.5*log((1+a)/(1-a)); fast log is safe here
        float ath = 0.5f * __logf(__fdividef(1.0f + arg, 1.0f - arg));
        float f   = __fdividef(ath, sxn);

        float un  = fmaxf(f * sqrtf(s2p), MIN_NORM);
        float sun = sqrt_c * un;
        float tt  = __fdividef(tanhf(sun), sun);

        float yn  = fmaxf(un * tt, MIN_NORM);
        float ps  = (yn > maxnorm) ? __fdividef(maxnorm, yn) : 1.0f;
        return f * tt * ps;
    };

    const float mA = row_scale(s2A, s2pA);
    const float mB = row_scale(s2B, s2pB);

    float4* opA = out + (size_t)rowA * 16 + lane;
    #pragma unroll
    for (int i = 0; i < 4; i++) {
        float4 o;
        o.x = fmaxf(v[i].x, 0.f) * mA;
        o.y = fmaxf(v[i].y, 0.f) * mA;
        o.z = fmaxf(v[i].z, 0.f) * mA;
        o.w = fmaxf(v[i].w, 0.f) * mA;
        __stcs(opA + i * 4, o);
    }
    if (rowB < nrows) {
        #pragma unroll
        for (int i = 0; i < 4; i++) {
            float4 o;
            o.x = fmaxf(v[4+i].x, 0.f) * mB;
            o.y = fmaxf(v[4+i].y, 0.f) * mB;
            o.z = fmaxf(v[4+i].z, 0.f) * mB;
            o.w = fmaxf(v[4+i].w, 0.f) * mB;
            __stcs(opA + 16 + i * 4, o);
        }
    }
}

extern "C" void kernel_launch(void* const* d_in, const int* in_sizes, int n_in,
                              void* d_out, int out_size)
{
    const float4* x = (const float4*)d_in[0];
    const float*  c = (const float*)d_in[1];
    float4* out = (float4*)d_out;

    int nrows  = in_sizes[0] / 64;
    // 128 rows per 256-thread block (2 rows per thread-group of 4)
    int blocks = (nrows + 127) / 128;
    act_hyp_kernel<<<blocks, 256>>>(x, c, out, nrows);
}

// round 4
// speedup vs baseline: 1.0002x; 1.0002x over previous
#include <cuda_runtime.h>

// Fused Poincare-ball: y = proj(expmap0(relu(logmap0(x))))
// 4 threads per row (D=64), 4 x float4 per thread (one row per 4-lane group).
// __launch_bounds__(256, 8) caps regs at 32 -> full 64-warp occupancy to
// maximize outstanding DRAM sectors.

#define MIN_NORM  1e-7f
#define BALL_EPS  4e-3f
#define ATANH_EPS 1e-7f

__global__ __launch_bounds__(256, 8)
void act_hyp_kernel(const float4* __restrict__ x,
                    const float* __restrict__ c,
                    float4* __restrict__ out,
                    int nrows)
{
    const int t    = blockIdx.x * blockDim.x + threadIdx.x;
    const int row  = t >> 2;
    if (row >= nrows) return;
    const int lane = t & 3;

    const float4* xp = x + (size_t)row * 16 + lane;

    // Front-batch 4 x LDG.128 (64 B of this row per thread)
    float4 v[4];
    #pragma unroll
    for (int i = 0; i < 4; i++) v[i] = __ldcs(xp + i * 4);

    // Squared sums of x and relu(x) in one pass
    float s2  = 0.0f;
    float s2p = 0.0f;
    #pragma unroll
    for (int i = 0; i < 4; i++) {
        float a0 = v[i].x, a1 = v[i].y, a2 = v[i].z, a3 = v[i].w;
        s2 = fmaf(a0, a0, s2); s2 = fmaf(a1, a1, s2);
        s2 = fmaf(a2, a2, s2); s2 = fmaf(a3, a3, s2);
        float b0 = fmaxf(a0, 0.0f), b1 = fmaxf(a1, 0.0f);
        float b2 = fmaxf(a2, 0.0f), b3 = fmaxf(a3, 0.0f);
        s2p = fmaf(b0, b0, s2p); s2p = fmaf(b1, b1, s2p);
        s2p = fmaf(b2, b2, s2p); s2p = fmaf(b3, b3, s2p);
    }

    // 4-lane xor reduction (groups of 4 aligned within the warp)
    #pragma unroll
    for (int off = 2; off >= 1; off >>= 1) {
        s2  += __shfl_xor_sync(0xFFFFFFFFu, s2,  off);
        s2p += __shfl_xor_sync(0xFFFFFFFFu, s2p, off);
    }

    const float sqrt_c = sqrtf(c[0]);

    // logmap0 scale: f = atanh(min(sc*xn, 1-eps)) / (sc*xn)
    // atanh(a) = 0.5*log((1+a)/(1-a)) via fast log (no cancellation here)
    float xn  = fmaxf(sqrtf(s2), MIN_NORM);
    float sxn = sqrt_c * xn;
    float arg = fminf(sxn, 1.0f - ATANH_EPS);
    float ath = 0.5f * __logf(__fdividef(1.0f + arg, 1.0f - arg));
    float f   = __fdividef(ath, sxn);

    // expmap0 scale: t = tanh(sc*un)/(sc*un), un = f*||relu(x)|| (clamped)
    float un  = fmaxf(f * sqrtf(s2p), MIN_NORM);
    float sun = sqrt_c * un;
    float tt  = __fdividef(tanhf(sun), sun);

    // proj: ||y|| = un * tt analytically (both factors > 0)
    float yn      = fmaxf(un * tt, MIN_NORM);
    float maxnorm = __fdividef(1.0f - BALL_EPS, sqrt_c);
    float ps      = (yn > maxnorm) ? __fdividef(maxnorm, yn) : 1.0f;

    const float m = f * tt * ps;

    float4* op = out + (size_t)row * 16 + lane;
    #pragma unroll
    for (int i = 0; i < 4; i++) {
        float4 o;
        o.x = fmaxf(v[i].x, 0.0f) * m;
        o.y = fmaxf(v[i].y, 0.0f) * m;
        o.z = fmaxf(v[i].z, 0.0f) * m;
        o.w = fmaxf(v[i].w, 0.0f) * m;
        __stcs(op + i * 4, o);
    }
}

extern "C" void kernel_launch(void* const* d_in, const int* in_sizes, int n_in,
                              void* d_out, int out_size)
{
    const float4* x = (const float4*)d_in[0];
    const float*  c = (const float*)d_in[1];
    float4* out = (float4*)d_out;

    int nrows  = in_sizes[0] / 64;
    int blocks = (nrows + 63) / 64;   // 64 rows per 256-thread block
    act_hyp_kernel<<<blocks, 256>>>(x, c, out, nrows);
}

// round 5
// speedup vs baseline: 1.0067x; 1.0065x over previous
#include <cuda_runtime.h>

// Fused Poincare-ball: y = proj(expmap0(relu(logmap0(x))))
// 4 threads per row (D=64), 4 x float4 per thread. Best-measured config (R2)
// with 512-thread blocks and branchless proj clamp. Kernel is at the mixed
// read/write HBM ceiling (~6.8 TB/s measured across occ/MLP variants).

#define MIN_NORM  1e-7f
#define BALL_EPS  4e-3f
#define ATANH_EPS 1e-7f

__global__ __launch_bounds__(512)
void act_hyp_kernel(const float4* __restrict__ x,
                    const float* __restrict__ c,
                    float4* __restrict__ out,
                    int nrows)
{
    const int t    = blockIdx.x * blockDim.x + threadIdx.x;
    const int row  = t >> 2;
    if (row >= nrows) return;
    const int lane = t & 3;

    const float4* xp = x + (size_t)row * 16 + lane;

    // Front-batch 4 x LDG.128 (64 B of this row per thread)
    float4 v[4];
    #pragma unroll
    for (int i = 0; i < 4; i++) v[i] = __ldcs(xp + i * 4);

    // relu'd copy + both squared sums in one pass
    float r[16];
    float s2  = 0.0f;
    float s2p = 0.0f;
    #pragma unroll
    for (int i = 0; i < 4; i++) {
        float a0 = v[i].x, a1 = v[i].y, a2 = v[i].z, a3 = v[i].w;
        s2 = fmaf(a0, a0, s2); s2 = fmaf(a1, a1, s2);
        s2 = fmaf(a2, a2, s2); s2 = fmaf(a3, a3, s2);
        float b0 = fmaxf(a0, 0.0f), b1 = fmaxf(a1, 0.0f);
        float b2 = fmaxf(a2, 0.0f), b3 = fmaxf(a3, 0.0f);
        s2p = fmaf(b0, b0, s2p); s2p = fmaf(b1, b1, s2p);
        s2p = fmaf(b2, b2, s2p); s2p = fmaf(b3, b3, s2p);
        r[i*4+0] = b0; r[i*4+1] = b1; r[i*4+2] = b2; r[i*4+3] = b3;
    }

    // 4-lane xor reduction (groups of 4 aligned within the warp)
    #pragma unroll
    for (int off = 2; off >= 1; off >>= 1) {
        s2  += __shfl_xor_sync(0xFFFFFFFFu, s2,  off);
        s2p += __shfl_xor_sync(0xFFFFFFFFu, s2p, off);
    }

    const float sqrt_c = sqrtf(c[0]);

    // logmap0 scale: f = atanh(min(sc*xn, 1-eps)) / (sc*xn)
    // atanh(a) = 0.5*log((1+a)/(1-a)) via fast log (no cancellation here)
    float xn  = fmaxf(sqrtf(s2), MIN_NORM);
    float sxn = sqrt_c * xn;
    float arg = fminf(sxn, 1.0f - ATANH_EPS);
    float ath = 0.5f * __logf(__fdividef(1.0f + arg, 1.0f - arg));
    float f   = __fdividef(ath, sxn);

    // expmap0 scale: t = tanh(sc*un)/(sc*un), un = f*||relu(x)|| (clamped)
    float un  = fmaxf(f * sqrtf(s2p), MIN_NORM);
    float sun = sqrt_c * un;
    float tt  = __fdividef(tanhf(sun), sun);

    // proj: ||y|| = un * tt analytically (both factors > 0); branchless clamp
    float yn      = fmaxf(un * tt, MIN_NORM);
    float maxnorm = __fdividef(1.0f - BALL_EPS, sqrt_c);
    float ps      = fminf(1.0f, __fdividef(maxnorm, yn));

    const float m = f * tt * ps;

    float4* op = out + (size_t)row * 16 + lane;
    #pragma unroll
    for (int i = 0; i < 4; i++) {
        float4 o;
        o.x = r[i*4+0] * m;
        o.y = r[i*4+1] * m;
        o.z = r[i*4+2] * m;
        o.w = r[i*4+3] * m;
        __stcs(op + i * 4, o);
    }
}

extern "C" void kernel_launch(void* const* d_in, const int* in_sizes, int n_in,
                              void* d_out, int out_size)
{
    const float4* x = (const float4*)d_in[0];
    const float*  c = (const float*)d_in[1];
    float4* out = (float4*)d_out;

    int nrows  = in_sizes[0] / 64;
    int blocks = (nrows + 127) / 128;   // 128 rows per 512-thread block
    act_hyp_kernel<<<blocks, 512>>>(x, c, out, nrows);
}